// round 8
// baseline (speedup 1.0000x reference)
#include <cuda_runtime.h>
#include <cstdint>

// =========================================================================
// EuclideanGraphDecoder on GB300 (sm_103a via compute_103 baseline PTX)
// B=8, N=2048, latent=64, hidden=128, out=64, NORM=1.
//
// R8: unified tf32 mma.sync GEMM, cp.async 4-stage pipeline, ONE barrier per
// chunk, ldmatrix.x4 A-fragment loads, ks-level fragment double buffering.
// =========================================================================

#define BATCH   8
#define NNODES  2048
#define HID     128
#define ROWS_T  (BATCH * NNODES)     // 16384

__device__ float g_buf0[ROWS_T * HID];     // msg (node-major, tf32-rounded)
__device__ float g_buf1[ROWS_T * HID];     // h   (node-major, fp32)

// ---------------------------------------------------------------- helpers
__device__ __forceinline__ uint32_t cvt_rna_tf32(float x) {
    uint32_t y;
    asm("cvt.rna.tf32.f32 %0, %1;" : "=r"(y) : "f"(x));
    return y;
}
__device__ __forceinline__ uint32_t cvt_rna_tf32_u(uint32_t x) {
    uint32_t y;
    asm("cvt.rna.tf32.f32 %0, %1;" : "=r"(y) : "r"(x));
    return y;
}
__device__ __forceinline__ uint32_t smem_u32(const void* p) {
    uint32_t a;
    asm("{ .reg .u64 t; cvta.to.shared.u64 t, %1; cvt.u32.u64 %0, t; }" : "=r"(a) : "l"(p));
    return a;
}
__device__ __forceinline__ void cp_async16(uint32_t dst, const void* src) {
    asm volatile("cp.async.cg.shared.global [%0], [%1], 16;" :: "r"(dst), "l"(src));
}
#define CP_COMMIT() asm volatile("cp.async.commit_group;" ::: "memory")

__device__ __forceinline__ void ldsm_x4(uint32_t& r0, uint32_t& r1, uint32_t& r2, uint32_t& r3,
                                        uint32_t addr) {
    asm volatile("ldmatrix.sync.aligned.m8n8.x4.shared.b16 {%0,%1,%2,%3}, [%4];"
                 : "=r"(r0), "=r"(r1), "=r"(r2), "=r"(r3) : "r"(addr));
}

__device__ __forceinline__ void mma_tf32(float& c0, float& c1, float& c2, float& c3,
                                         uint32_t a0, uint32_t a1, uint32_t a2, uint32_t a3,
                                         uint32_t b0, uint32_t b1) {
    asm volatile(
        "mma.sync.aligned.m16n8k8.row.col.f32.tf32.tf32.f32 "
        "{%0,%1,%2,%3}, {%4,%5,%6,%7}, {%8,%9}, {%0,%1,%2,%3};"
        : "+f"(c0), "+f"(c1), "+f"(c2), "+f"(c3)
        : "r"(a0), "r"(a1), "r"(a2), "r"(a3), "r"(b0), "r"(b1));
}

// =========================================================================
// Unified tf32 GEMM:  C[b, m0:m0+128, 0:128] = op( A[b,:,0:K] @ B[b,0:K,0:128] )
// CTA 128x128, BK=32 chunks, 4-stage cp.async, 8 warps 4(M)x2(N),
// warp tile 32x64 = 2x8 m16n8k8.
// A fragments: ldmatrix.x4 + in-register RNA->tf32 cvt.
// B fragments: LDS.32 (CVTB rounds them too, for raw weights).
// =========================================================================
#define BK      32
#define STG     4
#define ASTRIDE 36
#define BSTRIDE 136
#define A_FLTS  (128 * ASTRIDE)      // 4608
#define B_FLTS  (BK * BSTRIDE)       // 4352
#define STG_FLTS (A_FLTS + B_FLTS)   // 8960
#define STG_BYTES (STG_FLTS * 4)
#define GEMM_SMEM (STG * STG_BYTES)  // 143360 bytes

__device__ __forceinline__ void stage_chunk(uint32_t smb, int s,
                                            const float* Ap, const float* Bp,
                                            int k0, int tid, int lda)
{
    const uint32_t sa = smb + (uint32_t)s * STG_BYTES;
    const uint32_t sb = sa + A_FLTS * 4u;
#pragma unroll
    for (int r = 0; r < 4; r++) {
        const int idx  = tid + 256 * r;
        const int arow = idx >> 3, aseg = idx & 7;
        cp_async16(sa + (uint32_t)(arow * ASTRIDE + aseg * 4) * 4u,
                   Ap + (size_t)arow * lda + k0 + aseg * 4);
        const int brow = idx >> 5, bseg = idx & 31;
        cp_async16(sb + (uint32_t)(brow * BSTRIDE + bseg * 4) * 4u,
                   Bp + (size_t)(k0 + brow) * HID + bseg * 4);
    }
    CP_COMMIT();
}

template<bool RELU, bool BIAS, bool ROUND, bool CVTB>
__global__ __launch_bounds__(256, 1)
void mma_gemm_kernel(const float* __restrict__ A, const float* __restrict__ B,
                     const float* __restrict__ bias, float* __restrict__ C,
                     int K, int lda, size_t sA, size_t sB, size_t sC)
{
    extern __shared__ float smf[];
    const uint32_t smb = smem_u32(smf);

    const int tid   = threadIdx.x;
    const int lane  = tid & 31;
    const int wid   = tid >> 5;
    const int g     = lane >> 2;       // 0..7
    const int tig   = lane & 3;        // 0..3
    const int mbase = (wid & 3) * 32;  // 4 warps along M
    const int nbase = (wid >> 2) * 64; // 2 warps along N

    // ldmatrix per-thread source row/col inside the 16x8 fragment
    const int mi   = lane >> 3;               // matrix index 0..3
    const int arow = (lane & 7) + (mi & 1) * 8;
    const int acol = (mi >> 1) * 4;
    // byte offset (within a stage's A region) of this thread's LDSM row ptr, per t
    uint32_t a_off[2];
#pragma unroll
    for (int t = 0; t < 2; t++)
        a_off[t] = (uint32_t)(((mbase + t * 16 + arow) * ASTRIDE + acol) * 4);

    const int batch = blockIdx.y;
    const int m0    = blockIdx.x * 128;

    const float* Ap = A + (size_t)batch * sA + (size_t)m0 * lda;
    const float* Bp = B + (size_t)batch * sB;

    float acc[2][8][4];
#pragma unroll
    for (int t = 0; t < 2; t++)
#pragma unroll
        for (int u = 0; u < 8; u++)
#pragma unroll
            for (int q = 0; q < 4; q++) acc[t][u][q] = 0.0f;

    const int kiters = K / BK;

    int committed = 0;
#pragma unroll
    for (int p = 0; p < STG - 1; p++)
        if (p < kiters) { stage_chunk(smb, p, Ap, Bp, p * BK, tid, lda); committed++; }

    uint32_t af[2][2][4];   // [buf][t][4]
    uint32_t bf[2][8][2];   // [buf][u][2]

    for (int it = 0; it < kiters; it++) {
        const int pend = committed - it - 1;
        if (pend <= 0)      asm volatile("cp.async.wait_group 0;" ::: "memory");
        else if (pend == 1) asm volatile("cp.async.wait_group 1;" ::: "memory");
        else                asm volatile("cp.async.wait_group 2;" ::: "memory");
        __syncthreads();
        // (single barrier per chunk: the refill below writes stage (it+3)&3,
        // whose last reads happened at it-1 and are ordered by this barrier)

        if (it + STG - 1 < kiters) {
            stage_chunk(smb, (it + STG - 1) & (STG - 1), Ap, Bp, (it + STG - 1) * BK, tid, lda);
            committed++;
        }

        const uint32_t sa = smb + (uint32_t)(it & (STG - 1)) * STG_BYTES;
        const uint32_t* bsu = (const uint32_t*)(smf + (it & (STG - 1)) * STG_FLTS + A_FLTS);

        // prefetch fragments for ks=0 into buffer 0
#pragma unroll
        for (int t = 0; t < 2; t++) {
            ldsm_x4(af[0][t][0], af[0][t][1], af[0][t][2], af[0][t][3], sa + a_off[t]);
#pragma unroll
            for (int q = 0; q < 4; q++) af[0][t][q] = cvt_rna_tf32_u(af[0][t][q]);
        }
#pragma unroll
        for (int u = 0; u < 8; u++) {
            const int n = nbase + u * 8 + g;
            uint32_t b0 = bsu[tig * BSTRIDE + n];
            uint32_t b1 = bsu[(tig + 4) * BSTRIDE + n];
            if (CVTB) { b0 = cvt_rna_tf32_u(b0); b1 = cvt_rna_tf32_u(b1); }
            bf[0][u][0] = b0; bf[0][u][1] = b1;
        }

#pragma unroll
        for (int ks = 0; ks < 4; ks++) {
            const int cur = ks & 1;
            const int nxt = cur ^ 1;
            if (ks < 3) {
                const int k = (ks + 1) * 8;
#pragma unroll
                for (int t = 0; t < 2; t++) {
                    ldsm_x4(af[nxt][t][0], af[nxt][t][1], af[nxt][t][2], af[nxt][t][3],
                            sa + a_off[t] + (uint32_t)(k * 4));
#pragma unroll
                    for (int q = 0; q < 4; q++) af[nxt][t][q] = cvt_rna_tf32_u(af[nxt][t][q]);
                }
#pragma unroll
                for (int u = 0; u < 8; u++) {
                    const int n = nbase + u * 8 + g;
                    uint32_t b0 = bsu[(k + tig) * BSTRIDE + n];
                    uint32_t b1 = bsu[(k + tig + 4) * BSTRIDE + n];
                    if (CVTB) { b0 = cvt_rna_tf32_u(b0); b1 = cvt_rna_tf32_u(b1); }
                    bf[nxt][u][0] = b0; bf[nxt][u][1] = b1;
                }
            }
#pragma unroll
            for (int u = 0; u < 8; u++)
#pragma unroll
                for (int t = 0; t < 2; t++)
                    mma_tf32(acc[t][u][0], acc[t][u][1], acc[t][u][2], acc[t][u][3],
                             af[cur][t][0], af[cur][t][1], af[cur][t][2], af[cur][t][3],
                             bf[cur][u][0], bf[cur][u][1]);
        }
    }

    // ---- epilogue ----
    float* Cp = C + (size_t)batch * sC + (size_t)m0 * HID;
#pragma unroll
    for (int t = 0; t < 2; t++) {
        const int r0 = mbase + t * 16 + g;
#pragma unroll
        for (int u = 0; u < 8; u++) {
            const int c = nbase + u * 8 + 2 * tig;
            float v[4] = { acc[t][u][0], acc[t][u][1], acc[t][u][2], acc[t][u][3] };
            if (BIAS) {
                const float bc0 = bias[c], bc1 = bias[c + 1];
                v[0] += bc0; v[1] += bc1; v[2] += bc0; v[3] += bc1;
            }
#pragma unroll
            for (int q = 0; q < 4; q++) {
                if (RELU)  v[q] = fmaxf(v[q], 0.0f);
                if (ROUND) v[q] = __uint_as_float(cvt_rna_tf32(v[q]));
            }
            float2 v0 = { v[0], v[1] };
            float2 v1 = { v[2], v[3] };
            *(float2*)(Cp + (size_t)r0 * HID + c)       = v0;
            *(float2*)(Cp + (size_t)(r0 + 8) * HID + c) = v1;
        }
    }
}

// =========================================================================
// Output projection: out = (h @ Wout + bout) * mask     (fp32 FFMA)
// =========================================================================
__global__ __launch_bounds__(256)
void final_proj_kernel(const float* __restrict__ h, const float* __restrict__ W,
                       const float* __restrict__ bias, const float* __restrict__ mask,
                       float* __restrict__ out)
{
    __shared__ float Ws[128][64];
    __shared__ float xs[16][128];
    __shared__ float bs[64];

    const int tid = threadIdx.x;
    for (int i = tid; i < 2048; i += 256)
        ((float4*)&Ws[0][0])[i] = ((const float4*)W)[i];
    if (tid < 64) bs[tid] = bias[tid];

    const int row0 = blockIdx.x * 16;
    for (int i = tid; i < 512; i += 256)
        ((float4*)&xs[0][0])[i] = *(const float4*)(h + (size_t)row0 * 128 + i * 4);
    __syncthreads();

    const int rl = tid >> 4;
    const int c4 = (tid & 15) * 4;

    float acc[4];
#pragma unroll
    for (int q = 0; q < 4; q++) acc[q] = bs[c4 + q];

#pragma unroll 8
    for (int d = 0; d < 128; d++) {
        const float x = xs[rl][d];
        const float4 w = *(const float4*)&Ws[d][c4];
        acc[0] += x * w.x;
        acc[1] += x * w.y;
        acc[2] += x * w.z;
        acc[3] += x * w.w;
    }

    const float m = mask[row0 + rl];
    float4 v = {acc[0] * m, acc[1] * m, acc[2] * m, acc[3] * m};
    *(float4*)(out + (size_t)(row0 + rl) * 64 + c4) = v;
}

// =========================================================================
// Launcher
// =========================================================================
extern "C" void kernel_launch(void* const* d_in, const int* in_sizes, int n_in,
                              void* d_out, int out_size)
{
    const float* latent = (const float*)d_in[0];
    const float* adj    = (const float*)d_in[1];
    const float* mask   = (const float*)d_in[2];
    const float* W0     = (const float*)d_in[3];
    const float* b0     = (const float*)d_in[4];
    const float* W1     = (const float*)d_in[5];
    const float* b1     = (const float*)d_in[6];
    const float* W2     = (const float*)d_in[7];
    const float* b2     = (const float*)d_in[8];
    const float* Wout   = (const float*)d_in[9];
    const float* bout   = (const float*)d_in[10];
    float*       out    = (float*)d_out;

    float *buf0 = nullptr, *buf1 = nullptr;
    cudaGetSymbolAddress((void**)&buf0, g_buf0);
    cudaGetSymbolAddress((void**)&buf1, g_buf1);

    auto lin = mma_gemm_kernel<false, true, true, true>;    // bias + round, cvt weights
    auto agg = mma_gemm_kernel<true, false, false, false>;  // relu, B pre-rounded
    cudaFuncSetAttribute(lin, cudaFuncAttributeMaxDynamicSharedMemorySize, GEMM_SMEM);
    cudaFuncSetAttribute(agg, cudaFuncAttributeMaxDynamicSharedMemorySize, GEMM_SMEM);

    const dim3 gridLin(ROWS_T / 128, 1);       // 128 CTAs, batch folded into M
    const dim3 gridAgg(NNODES / 128, BATCH);   // 16 x 8 = 128 CTAs
    const size_t sAdj = (size_t)NNODES * NNODES;
    const size_t sH   = (size_t)NNODES * HID;

    // layer 0
    lin<<<gridLin, 256, GEMM_SMEM>>>(latent, W0, b0, buf0, 64, 64, 0, 0, 0);
    agg<<<gridAgg, 256, GEMM_SMEM>>>(adj, buf0, nullptr, buf1, NNODES, NNODES, sAdj, sH, sH);

    // layer 1
    lin<<<gridLin, 256, GEMM_SMEM>>>(buf1, W1, b1, buf0, 128, 128, 0, 0, 0);
    agg<<<gridAgg, 256, GEMM_SMEM>>>(adj, buf0, nullptr, buf1, NNODES, NNODES, sAdj, sH, sH);

    // layer 2
    lin<<<gridLin, 256, GEMM_SMEM>>>(buf1, W2, b2, buf0, 128, 128, 0, 0, 0);
    agg<<<gridAgg, 256, GEMM_SMEM>>>(adj, buf0, nullptr, buf1, NNODES, NNODES, sAdj, sH, sH);

    // output projection + mask
    final_proj_kernel<<<ROWS_T / 16, 256>>>(buf1, Wout, bout, mask, out);
}